// round 5
// baseline (speedup 1.0000x reference)
#include <cuda_runtime.h>
#include <cuda_fp16.h>
#include <cstdint>

#define NB   8
#define IC   512
#define OC   512
#define PX   4096
#define KTOT 4608
#define NKS  288           // KTOT / 16

// ---------------- scratch (device globals; no allocation) ----------------
__device__ float g_smod[NB * IC];
__device__ float g_s2[NB * IC];
__device__ float g_sig[NB * OC];
__device__ __half g_Ahi[(size_t)NB * OC * KTOT];     // [b][o][k]
__device__ __half g_Alo[(size_t)NB * OC * KTOT];

// ---------------- baseline-PTX helpers (valid on plain sm_103) ----------------
__device__ __forceinline__ void cp16(uint32_t dst, const void* src) {
    asm volatile("cp.async.cg.shared.global [%0], [%1], 16;" :: "r"(dst), "l"(src));
}
__device__ __forceinline__ void cp_commit() {
    asm volatile("cp.async.commit_group;" ::: "memory");
}
__device__ __forceinline__ void cp_wait2() {
    asm volatile("cp.async.wait_group 2;" ::: "memory");
}
__device__ __forceinline__ void ldsm4(uint32_t* r, uint32_t a) {
    asm volatile("ldmatrix.sync.aligned.m8n8.x4.shared.b16 {%0,%1,%2,%3}, [%4];"
                 : "=r"(r[0]), "=r"(r[1]), "=r"(r[2]), "=r"(r[3]) : "r"(a));
}
__device__ __forceinline__ void ldsm4t(uint32_t* r, uint32_t a) {
    asm volatile("ldmatrix.sync.aligned.m8n8.x4.trans.shared.b16 {%0,%1,%2,%3}, [%4];"
                 : "=r"(r[0]), "=r"(r[1]), "=r"(r[2]), "=r"(r[3]) : "r"(a));
}
__device__ __forceinline__ void mma16816(float* c, const uint32_t* a, const uint32_t* b) {
    asm volatile(
        "mma.sync.aligned.m16n8k16.row.col.f32.f16.f16.f32 "
        "{%0,%1,%2,%3},{%4,%5,%6,%7},{%8,%9},{%0,%1,%2,%3};"
        : "+f"(c[0]), "+f"(c[1]), "+f"(c[2]), "+f"(c[3])
        : "r"(a[0]), "r"(a[1]), "r"(a[2]), "r"(a[3]), "r"(b[0]), "r"(b[1]));
}

// ---------------------------------------------------------------------------
// K1: style  s[b,i] = latent.w_lin * C_LIN + b_lin   (warp per output i)
// ---------------------------------------------------------------------------
__global__ void k_style(const float* __restrict__ latent,
                        const float* __restrict__ w_lin,
                        const float* __restrict__ b_lin) {
    __shared__ float lat[512];
    const int b = blockIdx.x;
    const int tid = threadIdx.x, lane = tid & 31;
    lat[tid]       = latent[b * 512 + tid];
    lat[tid + 256] = latent[b * 512 + tid + 256];
    __syncthreads();
    const int i = blockIdx.y * 8 + (tid >> 5);
    const float4* wr = (const float4*)(w_lin + (size_t)i * 512);
    float acc = 0.f;
#pragma unroll
    for (int t = 0; t < 4; ++t) {
        float4 v = __ldg(wr + lane + t * 32);
        int j0 = (lane + t * 32) * 4;
        acc += v.x * lat[j0] + v.y * lat[j0 + 1] + v.z * lat[j0 + 2] + v.w * lat[j0 + 3];
    }
#pragma unroll
    for (int st = 16; st > 0; st >>= 1) acc += __shfl_xor_sync(0xffffffffu, acc, st);
    if (lane == 0) {
        const float C_LIN  = 0.04419417382415922f;   // 1/sqrt(512)
        const float C_CONV = 0.014731391274719742f;  // 1/sqrt(4608)
        float s = acc * C_LIN + b_lin[i];
        g_smod[b * 512 + i] = s * C_CONV;
        g_s2[b * 512 + i]   = s * s;
    }
}

// ---------------------------------------------------------------------------
// K2: sigma_inv[b,o]
// ---------------------------------------------------------------------------
__global__ void k_sigma(const float* __restrict__ w_conv) {
    __shared__ float red[8][128];
    const int o = blockIdx.x;
    const int tid = threadIdx.x;
    float acc[8];
#pragma unroll
    for (int b = 0; b < 8; ++b) acc[b] = 0.f;
    for (int i = tid; i < 512; i += 128) {
        const float* wp = w_conv + ((size_t)o * 512 + i) * 9;
        float ws = 0.f;
#pragma unroll
        for (int t = 0; t < 9; ++t) { float v = wp[t]; ws += v * v; }
#pragma unroll
        for (int b = 0; b < 8; ++b) acc[b] += ws * g_s2[b * 512 + i];
    }
#pragma unroll
    for (int b = 0; b < 8; ++b) red[b][tid] = acc[b];
    __syncthreads();
    for (int st = 64; st > 0; st >>= 1) {
        if (tid < st) {
#pragma unroll
            for (int b = 0; b < 8; ++b) red[b][tid] += red[b][tid + st];
        }
        __syncthreads();
    }
    if (tid < 8) {
        const float C2 = 1.0f / 4608.0f;
        g_sig[tid * 512 + o] = rsqrtf(red[tid][0] * C2 + 1e-8f);
    }
}

// ---------------------------------------------------------------------------
// K3: modulated weights -> fp16 hi/lo planes  [b][o][k]  (16B stores)
// ---------------------------------------------------------------------------
__global__ void k_moda(const float* __restrict__ w_conv) {
    const int o = blockIdx.x, b = blockIdx.y;
    const float* wr = w_conv + (size_t)o * KTOT;
    const float* sm = g_smod + b * IC;
    __half* ah = g_Ahi + ((size_t)(b * OC + o)) * KTOT;
    __half* al = g_Alo + ((size_t)(b * OC + o)) * KTOT;
    for (int g = threadIdx.x; g < KTOT / 8; g += 256) {
        const int k0 = g * 8;
        __half hv[8], lv[8];
#pragma unroll
        for (int e = 0; e < 8; ++e) {
            int k = k0 + e;
            float a = __ldg(wr + k) * sm[k / 9];
            __half hi = __float2half_rn(a);
            hv[e] = hi;
            lv[e] = __float2half_rn(a - __half2float(hi));
        }
        *(uint4*)(ah + k0) = *(const uint4*)hv;
        *(uint4*)(al + k0) = *(const uint4*)lv;
    }
}

// ---------------------------------------------------------------------------
// K4: GEMM with fused im2col.  BM=128 x BN=256 x BK=16, 512 threads / 16 warps.
// A (fp16 hi/lo) via 4-stage cp.async:  A[4][128][40] halfs (hi16|lo16|pad8)
// B (fp16 single plane) built in-kernel from x: 2 buffers [16][264] halfs
// D = Ahi*B + Alo*B  (2 MMAs per k16 fragment pair)
// ---------------------------------------------------------------------------
#define A_ST   10240
#define B_ST   8448
#define B_OFF  40960
#define SMEM_TOTAL (B_OFF + 2 * B_ST)   // 57,856

__global__ void __launch_bounds__(512, 1)
k_gemm(const float* __restrict__ x, const float* __restrict__ b_conv,
       float* __restrict__ out) {
    extern __shared__ char smem[];
    const uint32_t sb = (uint32_t)__cvta_generic_to_shared(smem);
    const int tid = threadIdx.x, wid = tid >> 5, lane = tid & 31;
    const int mt = blockIdx.x, nt = blockIdx.y, b = blockIdx.z;
    const int o0 = mt * 128, p0 = nt * 256;
    const int wm = (wid >> 2) * 32, wn = (wid & 3) * 64;

    // -------- A cp.async mapping: 1 cp16/thread --------
    const int arow = tid >> 2, aseg = tid & 3;        // seg: plane*2 + half
    const int apl = aseg >> 1, ahalf = aseg & 1;
    const __half* asrc =
        (apl ? g_Alo : g_Ahi) + ((size_t)(b * OC + o0 + arow)) * KTOT + ahalf * 8;
    const uint32_t adst = sb + (uint32_t)(arow * 80 + apl * 32 + ahalf * 16);

    auto issueA = [&](int s) {
        cp16(adst + (s & 3) * A_ST, asrc + s * 16);
    };

    // -------- fused im2col B build: 8 px/thread/stage --------
    const int bkk  = tid >> 5;            // k-row 0..15
    const int bseg = tid & 31;            // 32 px-segments of 8
    const int r0   = p0 >> 6;             // base image row of this N-tile
    const int lr   = bseg >> 3;           // 0..3 rows within tile
    const int wseg = (bseg & 7) << 3;     // 0..56
    const float* xb = x + ((size_t)b * IC << 12);

    auto buildB = [&](int s, int buf) {
        const int k = s * 16 + bkk;
        const int ci = k / 9;
        const int t  = k - ci * 9;
        const int dy = t / 3 - 1;
        const int dx = t - (t / 3) * 3 - 1;
        const int h  = r0 + lr + dy;
        const int w0 = wseg + dx;
        float v[8];
        if ((unsigned)h < 64u) {
            const float* row = xb + ((size_t)ci << 12) + (h << 6);
#pragma unroll
            for (int e = 0; e < 8; ++e) {
                int w = w0 + e;
                v[e] = ((unsigned)w < 64u) ? __ldg(row + w) : 0.f;
            }
        } else {
#pragma unroll
            for (int e = 0; e < 8; ++e) v[e] = 0.f;
        }
        __half2 hv[4];
#pragma unroll
        for (int q = 0; q < 4; ++q) hv[q] = __floats2half2_rn(v[2 * q], v[2 * q + 1]);
        *(uint4*)(smem + B_OFF + buf * B_ST + (bkk * 264 + bseg * 8) * 2) =
            *(const uint4*)hv;
    };

    // -------- ldmatrix lane offsets --------
    const uint32_t a_lane = (uint32_t)((lane & 15) * 80 + (lane >> 4) * 16);
    const uint32_t b_lane = (uint32_t)((((lane & 7) + ((lane >> 3) & 1) * 8) * 264 +
                                       ((lane >> 4) << 3)) * 2);

    float acc[2][8][4];
#pragma unroll
    for (int mi = 0; mi < 2; ++mi)
#pragma unroll
        for (int j = 0; j < 8; ++j)
#pragma unroll
            for (int q = 0; q < 4; ++q) acc[mi][j][q] = 0.f;

    issueA(0); cp_commit();
    issueA(1); cp_commit();
    issueA(2); cp_commit();
    buildB(0, 0);

#pragma unroll 1
    for (int s = 0; s < NKS; ++s) {
        cp_wait2();
        __syncthreads();
        if (s + 3 < NKS) issueA(s + 3);
        cp_commit();
        if (s + 1 < NKS) buildB(s + 1, (s + 1) & 1);

        const uint32_t ab = sb + (s & 3) * A_ST;
        const uint32_t bb = sb + B_OFF + (s & 1) * B_ST;

        uint32_t ahi[2][4], alo[2][4];
#pragma unroll
        for (int mi = 0; mi < 2; ++mi) {
            uint32_t ad = ab + (uint32_t)((wm + mi * 16) * 80) + a_lane;
            ldsm4(ahi[mi], ad);
            ldsm4(alo[mi], ad + 32);
        }
#pragma unroll
        for (int n2 = 0; n2 < 4; ++n2) {
            uint32_t bf[4];
            ldsm4t(bf, bb + (uint32_t)((wn + n2 * 16) * 2) + b_lane);
#pragma unroll
            for (int mi = 0; mi < 2; ++mi)
#pragma unroll
                for (int nf = 0; nf < 2; ++nf) {
                    float* c = acc[mi][n2 * 2 + nf];
                    mma16816(c, ahi[mi], &bf[nf * 2]);
                    mma16816(c, alo[mi], &bf[nf * 2]);
                }
        }
    }

    // -------- epilogue: demodulate + bias --------
    const int row_l = lane >> 2, col_l = (lane & 3) * 2;
#pragma unroll
    for (int mi = 0; mi < 2; ++mi) {
        const int oa = o0 + wm + mi * 16 + row_l;
        const int ob = oa + 8;
        const float sa = g_sig[b * OC + oa], ba = b_conv[oa];
        const float sc = g_sig[b * OC + ob], bc = b_conv[ob];
        float* ra = out + (((size_t)(b * OC + oa)) << 12) + p0 + wn + col_l;
        float* rb = out + (((size_t)(b * OC + ob)) << 12) + p0 + wn + col_l;
#pragma unroll
        for (int j = 0; j < 8; ++j) {
            float2 v0, v1;
            v0.x = acc[mi][j][0] * sa + ba;
            v0.y = acc[mi][j][1] * sa + ba;
            v1.x = acc[mi][j][2] * sc + bc;
            v1.y = acc[mi][j][3] * sc + bc;
            *(float2*)(ra + j * 8) = v0;
            *(float2*)(rb + j * 8) = v1;
        }
    }
}

// ---------------------------------------------------------------------------
extern "C" void kernel_launch(void* const* d_in, const int* in_sizes, int n_in,
                              void* d_out, int out_size) {
    const float* x      = (const float*)d_in[0];
    const float* latent = (const float*)d_in[1];
    const float* w_lin  = (const float*)d_in[2];
    const float* b_lin  = (const float*)d_in[3];
    const float* w_conv = (const float*)d_in[4];
    const float* b_conv = (const float*)d_in[5];
    float* out = (float*)d_out;

    cudaFuncSetAttribute(k_gemm, cudaFuncAttributeMaxDynamicSharedMemorySize, SMEM_TOTAL);

    k_style<<<dim3(NB, 64), 256>>>(latent, w_lin, b_lin);
    k_sigma<<<OC, 128>>>(w_conv);
    k_moda<<<dim3(OC, NB), 256>>>(w_conv);
    k_gemm<<<dim3(4, 16, NB), 512, SMEM_TOTAL>>>(x, b_conv, out);
}

// round 6
// speedup vs baseline: 1.2636x; 1.2636x over previous
#include <cuda_runtime.h>
#include <cuda_fp16.h>
#include <cstdint>

#define NB   8
#define IC   512
#define OC   512
#define PX   4096
#define KTOT 4608
#define NKS  288           // KTOT / 16

// ---------------- scratch (device globals; no allocation) ----------------
__device__ float g_smod[NB * IC];
__device__ float g_s2[NB * IC];
__device__ float g_sig[NB * OC];
__device__ __half g_Ahi[(size_t)NB * OC * KTOT];     // [b][o][k]
__device__ __half g_Alo[(size_t)NB * OC * KTOT];

// ---------------- baseline-PTX helpers (valid on plain sm_103) ----------------
__device__ __forceinline__ void cp16(uint32_t dst, const void* src) {
    asm volatile("cp.async.cg.shared.global [%0], [%1], 16;" :: "r"(dst), "l"(src));
}
__device__ __forceinline__ void cp_commit() {
    asm volatile("cp.async.commit_group;" ::: "memory");
}
__device__ __forceinline__ void cp_wait2() {
    asm volatile("cp.async.wait_group 2;" ::: "memory");
}
__device__ __forceinline__ void ldsm4(uint32_t* r, uint32_t a) {
    asm volatile("ldmatrix.sync.aligned.m8n8.x4.shared.b16 {%0,%1,%2,%3}, [%4];"
                 : "=r"(r[0]), "=r"(r[1]), "=r"(r[2]), "=r"(r[3]) : "r"(a));
}
__device__ __forceinline__ void ldsm4t(uint32_t* r, uint32_t a) {
    asm volatile("ldmatrix.sync.aligned.m8n8.x4.trans.shared.b16 {%0,%1,%2,%3}, [%4];"
                 : "=r"(r[0]), "=r"(r[1]), "=r"(r[2]), "=r"(r[3]) : "r"(a));
}
__device__ __forceinline__ void mma16816(float* c, const uint32_t* a, const uint32_t* b) {
    asm volatile(
        "mma.sync.aligned.m16n8k16.row.col.f32.f16.f16.f32 "
        "{%0,%1,%2,%3},{%4,%5,%6,%7},{%8,%9},{%0,%1,%2,%3};"
        : "+f"(c[0]), "+f"(c[1]), "+f"(c[2]), "+f"(c[3])
        : "r"(a[0]), "r"(a[1]), "r"(a[2]), "r"(a[3]), "r"(b[0]), "r"(b[1]));
}

// ---------------------------------------------------------------------------
// K1: style  s[b,i] = latent.w_lin * C_LIN + b_lin   (warp per output i)
// ---------------------------------------------------------------------------
__global__ void k_style(const float* __restrict__ latent,
                        const float* __restrict__ w_lin,
                        const float* __restrict__ b_lin) {
    __shared__ float lat[512];
    const int b = blockIdx.x;
    const int tid = threadIdx.x, lane = tid & 31;
    lat[tid]       = latent[b * 512 + tid];
    lat[tid + 256] = latent[b * 512 + tid + 256];
    __syncthreads();
    const int i = blockIdx.y * 8 + (tid >> 5);
    const float4* wr = (const float4*)(w_lin + (size_t)i * 512);
    float acc = 0.f;
#pragma unroll
    for (int t = 0; t < 4; ++t) {
        float4 v = __ldg(wr + lane + t * 32);
        int j0 = (lane + t * 32) * 4;
        acc += v.x * lat[j0] + v.y * lat[j0 + 1] + v.z * lat[j0 + 2] + v.w * lat[j0 + 3];
    }
#pragma unroll
    for (int st = 16; st > 0; st >>= 1) acc += __shfl_xor_sync(0xffffffffu, acc, st);
    if (lane == 0) {
        const float C_LIN  = 0.04419417382415922f;   // 1/sqrt(512)
        const float C_CONV = 0.014731391274719742f;  // 1/sqrt(4608)
        float s = acc * C_LIN + b_lin[i];
        g_smod[b * 512 + i] = s * C_CONV;
        g_s2[b * 512 + i]   = s * s;
    }
}

// ---------------------------------------------------------------------------
// K2: sigma_inv[b,o]
// ---------------------------------------------------------------------------
__global__ void k_sigma(const float* __restrict__ w_conv) {
    __shared__ float red[8][128];
    const int o = blockIdx.x;
    const int tid = threadIdx.x;
    float acc[8];
#pragma unroll
    for (int b = 0; b < 8; ++b) acc[b] = 0.f;
    for (int i = tid; i < 512; i += 128) {
        const float* wp = w_conv + ((size_t)o * 512 + i) * 9;
        float ws = 0.f;
#pragma unroll
        for (int t = 0; t < 9; ++t) { float v = wp[t]; ws += v * v; }
#pragma unroll
        for (int b = 0; b < 8; ++b) acc[b] += ws * g_s2[b * 512 + i];
    }
#pragma unroll
    for (int b = 0; b < 8; ++b) red[b][tid] = acc[b];
    __syncthreads();
    for (int st = 64; st > 0; st >>= 1) {
        if (tid < st) {
#pragma unroll
            for (int b = 0; b < 8; ++b) red[b][tid] += red[b][tid + st];
        }
        __syncthreads();
    }
    if (tid < 8) {
        const float C2 = 1.0f / 4608.0f;
        g_sig[tid * 512 + o] = rsqrtf(red[tid][0] * C2 + 1e-8f);
    }
}

// ---------------------------------------------------------------------------
// K3: modulated weights -> fp16 hi/lo planes  [b][o][k]  (16B stores)
// ---------------------------------------------------------------------------
__global__ void k_moda(const float* __restrict__ w_conv) {
    const int o = blockIdx.x, b = blockIdx.y;
    const float* wr = w_conv + (size_t)o * KTOT;
    const float* sm = g_smod + b * IC;
    __half* ah = g_Ahi + ((size_t)(b * OC + o)) * KTOT;
    __half* al = g_Alo + ((size_t)(b * OC + o)) * KTOT;
    for (int g = threadIdx.x; g < KTOT / 8; g += 256) {
        const int k0 = g * 8;
        __half hv[8], lv[8];
#pragma unroll
        for (int e = 0; e < 8; ++e) {
            int k = k0 + e;
            float a = __ldg(wr + k) * sm[k / 9];
            __half hi = __float2half_rn(a);
            hv[e] = hi;
            lv[e] = __float2half_rn(a - __half2float(hi));
        }
        *(uint4*)(ah + k0) = *(const uint4*)hv;
        *(uint4*)(al + k0) = *(const uint4*)lv;
    }
}

// ---------------------------------------------------------------------------
// K4: GEMM with fused + register-pipelined im2col.
// BM=128 x BN=256 x BK=16, 512 threads / 16 warps (warp tile 32x64).
// A (fp16 hi/lo) via 4-stage cp.async:  A[4][128][40] halfs (hi16|lo16|pad8)
// B built from x with LDG issued one full stage ahead of its STS:
//   iter s:  bar -> STS(bv -> buf s+1) -> LDG(bv <- stage s+2) -> MMA(stage s)
// D = Ahi*B + Alo*B
// ---------------------------------------------------------------------------
#define A_ST   10240
#define B_ST   8448
#define B_OFF  40960
#define SMEM_TOTAL (B_OFF + 2 * B_ST)   // 57,856

__global__ void __launch_bounds__(512, 1)
k_gemm(const float* __restrict__ x, const float* __restrict__ b_conv,
       float* __restrict__ out) {
    extern __shared__ char smem[];
    const uint32_t sb = (uint32_t)__cvta_generic_to_shared(smem);
    const int tid = threadIdx.x, wid = tid >> 5, lane = tid & 31;
    const int mt = blockIdx.x, nt = blockIdx.y, b = blockIdx.z;
    const int o0 = mt * 128, p0 = nt * 256;
    const int wm = (wid >> 2) * 32, wn = (wid & 3) * 64;

    // -------- A cp.async mapping: 1 cp16/thread --------
    const int arow = tid >> 2, aseg = tid & 3;
    const int apl = aseg >> 1, ahalf = aseg & 1;
    const __half* asrc =
        (apl ? g_Alo : g_Ahi) + ((size_t)(b * OC + o0 + arow)) * KTOT + ahalf * 8;
    const uint32_t adst = sb + (uint32_t)(arow * 80 + apl * 32 + ahalf * 16);

    auto issueA = [&](int s) {
        cp16(adst + (s & 3) * A_ST, asrc + s * 16);
    };

    // -------- fused im2col, register-pipelined --------
    const int bkk  = tid >> 5;            // k-row 0..15
    const int bseg = tid & 31;            // 32 px-segments of 8
    const int r0   = p0 >> 6;
    const int lr   = bseg >> 3;           // 0..3 rows within tile
    const int wseg = (bseg & 7) << 3;     // 0..56
    const float* xb = x + ((size_t)b * IC << 12);
    const uint32_t bsts = sb + B_OFF + (uint32_t)(bkk * 264 + bseg * 8) * 2;

    float bv[8];                           // data for stage s+1, loaded in iter s-1

    auto loadB = [&](int s) {              // LDG stage s -> bv
        const int k = s * 16 + bkk;
        const int ci = k / 9;
        const int t  = k - ci * 9;
        const int dy = t / 3 - 1;
        const int dx = t - (t / 3) * 3 - 1;
        const int h  = r0 + lr + dy;
        const int w0 = wseg + dx;
        if ((unsigned)h < 64u) {
            const float* row = xb + ((size_t)ci << 12) + (h << 6);
#pragma unroll
            for (int e = 0; e < 8; ++e) {
                int w = w0 + e;
                bv[e] = ((unsigned)w < 64u) ? __ldg(row + w) : 0.f;
            }
        } else {
#pragma unroll
            for (int e = 0; e < 8; ++e) bv[e] = 0.f;
        }
    };
    auto stsB = [&](int buf) {             // cvt + STS bv -> buffer
        __half2 hv[4];
#pragma unroll
        for (int q = 0; q < 4; ++q) hv[q] = __floats2half2_rn(bv[2 * q], bv[2 * q + 1]);
        *(uint4*)((char*)smem + (bsts - sb) + buf * B_ST) = *(const uint4*)hv;
    };

    // -------- ldmatrix lane offsets --------
    const uint32_t a_lane = (uint32_t)((lane & 15) * 80 + (lane >> 4) * 16);
    const uint32_t b_lane = (uint32_t)((((lane & 7) + ((lane >> 3) & 1) * 8) * 264 +
                                       ((lane >> 4) << 3)) * 2);

    float acc[2][8][4];
#pragma unroll
    for (int mi = 0; mi < 2; ++mi)
#pragma unroll
        for (int j = 0; j < 8; ++j)
#pragma unroll
            for (int q = 0; q < 4; ++q) acc[mi][j][q] = 0.f;

    issueA(0); cp_commit();
    issueA(1); cp_commit();
    issueA(2); cp_commit();
    loadB(0); stsB(0);                     // stage 0 -> buf 0
    loadB(1);                              // stage 1 -> bv

#pragma unroll 1
    for (int s = 0; s < NKS; ++s) {
        cp_wait2();
        __syncthreads();
        if (s + 1 < NKS) stsB((s + 1) & 1);   // bv = stage s+1 (LDG landed long ago)
        if (s + 3 < NKS) issueA(s + 3);
        cp_commit();
        if (s + 2 < NKS) loadB(s + 2);        // latency hidden by stage-s MMAs

        const uint32_t ab = sb + (s & 3) * A_ST;
        const uint32_t bb = sb + B_OFF + (s & 1) * B_ST;

        uint32_t ahi[2][4], alo[2][4];
#pragma unroll
        for (int mi = 0; mi < 2; ++mi) {
            uint32_t ad = ab + (uint32_t)((wm + mi * 16) * 80) + a_lane;
            ldsm4(ahi[mi], ad);
            ldsm4(alo[mi], ad + 32);
        }
#pragma unroll
        for (int n2 = 0; n2 < 4; ++n2) {
            uint32_t bf[4];
            ldsm4t(bf, bb + (uint32_t)((wn + n2 * 16) * 2) + b_lane);
#pragma unroll
            for (int mi = 0; mi < 2; ++mi)
#pragma unroll
                for (int nf = 0; nf < 2; ++nf) {
                    float* c = acc[mi][n2 * 2 + nf];
                    mma16816(c, ahi[mi], &bf[nf * 2]);
                    mma16816(c, alo[mi], &bf[nf * 2]);
                }
        }
    }

    // -------- epilogue: demodulate + bias --------
    const int row_l = lane >> 2, col_l = (lane & 3) * 2;
#pragma unroll
    for (int mi = 0; mi < 2; ++mi) {
        const int oa = o0 + wm + mi * 16 + row_l;
        const int ob = oa + 8;
        const float sa = g_sig[b * OC + oa], ba = b_conv[oa];
        const float sc = g_sig[b * OC + ob], bc = b_conv[ob];
        float* ra = out + (((size_t)(b * OC + oa)) << 12) + p0 + wn + col_l;
        float* rb = out + (((size_t)(b * OC + ob)) << 12) + p0 + wn + col_l;
#pragma unroll
        for (int j = 0; j < 8; ++j) {
            float2 v0, v1;
            v0.x = acc[mi][j][0] * sa + ba;
            v0.y = acc[mi][j][1] * sa + ba;
            v1.x = acc[mi][j][2] * sc + bc;
            v1.y = acc[mi][j][3] * sc + bc;
            *(float2*)(ra + j * 8) = v0;
            *(float2*)(rb + j * 8) = v1;
        }
    }
}

// ---------------------------------------------------------------------------
extern "C" void kernel_launch(void* const* d_in, const int* in_sizes, int n_in,
                              void* d_out, int out_size) {
    const float* x      = (const float*)d_in[0];
    const float* latent = (const float*)d_in[1];
    const float* w_lin  = (const float*)d_in[2];
    const float* b_lin  = (const float*)d_in[3];
    const float* w_conv = (const float*)d_in[4];
    const float* b_conv = (const float*)d_in[5];
    float* out = (float*)d_out;

    cudaFuncSetAttribute(k_gemm, cudaFuncAttributeMaxDynamicSharedMemorySize, SMEM_TOTAL);

    k_style<<<dim3(NB, 64), 256>>>(latent, w_lin, b_lin);
    k_sigma<<<OC, 128>>>(w_conv);
    k_moda<<<dim3(OC, NB), 256>>>(w_conv);
    k_gemm<<<dim3(4, 16, NB), 512, SMEM_TOTAL>>>(x, b_conv, out);
}